// round 16
// baseline (speedup 1.0000x reference)
#include <cuda_runtime.h>
#include <cuda_bf16.h>

// ---------------------------------------------------------------------------
// BiLSTM-CRF forward loss.  B=64, T=512, V=50000, E=256, H=256, L=9.
// embed -> gemm(gx,l0,f32x2) -> lstm(l0: 64 CTAs x 2 interleaved groups,
//   half-step publish/release, per-warp L2 h-exchange, fused combine+update)
//   -> gemm/lstm(l1) -> linear -> CRF NLL -> mean.
// ---------------------------------------------------------------------------

#define Bsz  64
#define Tlen 512
#define Emb  256
#define Hd   256
#define Lnum 9
#define BT   (Bsz * Tlen)   // 32768

// dynamic smem layout for k_lstm (float offsets)
#define SM_W    0          // [32768] w slice (rank): [k/4][128 cols][4], unit-major
#define SM_HL   32768      // [2 grp][8 b][256 k]
#define SM_PART 36864      // [2 grp][4 kq][8 b][128 col]
#define SM_BYTES ((SM_PART + 2 * 4096) * 4)   // 180,224 B

#define FPAD 32            // ints per flag (one 128 B line each)

// -------------------- scratch (device globals; no allocs) -------------------
__device__ float g_x0[(size_t)BT * Emb];
__device__ float g_gx[2ull * BT * 1024];
__device__ float g_y0[(size_t)BT * 512];
__device__ float g_y1[(size_t)BT * 512];
__device__ float g_wt0[2 * 256 * 1024];
__device__ float g_wt1[2 * 256 * 1024];
__device__ float g_em[(size_t)BT * Lnum];
__device__ float g_partial[Bsz];
// h exchange: [d][g][buf][8 ranks][[ub(8)][ujj(32)]]
__device__ float g_hx[2 * 8 * 2 * 2048];
__device__ int   g_flag[2 * 8 * 8 * FPAD];

__device__ __forceinline__ float sigm(float x) { return 1.0f / (1.0f + __expf(-x)); }

__device__ __forceinline__ void fma2(unsigned long long& acc,
                                     unsigned long long a, unsigned long long b) {
    asm("fma.rn.f32x2 %0, %1, %2, %0;" : "+l"(acc) : "l"(a), "l"(b));
}
__device__ __forceinline__ unsigned long long pack2(float f) {
    unsigned long long r;
    asm("mov.b64 %0, {%1, %1};" : "=l"(r) : "f"(f));
    return r;
}
__device__ __forceinline__ unsigned long long packpair(float lo, float hi) {
    unsigned long long r;
    asm("mov.b64 %0, {%1, %2};" : "=l"(r) : "f"(lo), "f"(hi));
    return r;
}
__device__ __forceinline__ void unpack2(unsigned long long v, float& lo, float& hi) {
    asm("mov.b64 {%0, %1}, %2;" : "=f"(lo), "=f"(hi) : "l"(v));
}
__device__ __forceinline__ void flag_store_release(int* p, int v) {
    asm volatile("st.release.gpu.s32 [%0], %1;" :: "l"(p), "r"(v) : "memory");
}
__device__ __forceinline__ int flag_load_acquire(const int* p) {
    int v;
    asm volatile("ld.acquire.gpu.s32 %0, [%1];" : "=r"(v) : "l"(p) : "memory");
    return v;
}

// -------------------- 1) embedding gather (float4) --------------------------
__global__ void k_embed(const int* __restrict__ ids, const float* __restrict__ emb) {
    int i = blockIdx.x * blockDim.x + threadIdx.x;
    if (i >= BT * (Emb / 4)) return;
    int pos = i >> 6;
    int e4  = i & 63;
    ((float4*)g_x0)[i] = ((const float4*)emb)[(size_t)ids[pos] * (Emb / 4) + e4];
}

// -------- 2) w_hh relayout: [2][1024][256] -> [d][rank][k/4][128 cols][4] ----
// Column order within a rank is UNIT-MAJOR: c = unit*4 + gate.  Flags zeroed.
__global__ void k_trans(const float* __restrict__ w, int layer) {
    int i = blockIdx.x * blockDim.x + threadIdx.x;
    if (i < 2 * 8 * 8 * FPAD) g_flag[i] = 0;
    if (i >= 2 * 1024 * 256) return;
    int d   = i >> 18;
    int row = (i >> 8) & 1023;
    int k   = i & 255;
    int g   = row >> 8;            // gate 0..3 (i,f,g,o)
    int r   = (row & 255) >> 5;    // rank
    int jj  = row & 31;            // unit within rank
    int c   = jj * 4 + g;          // unit-major column
    float* dst = layer ? g_wt1 : g_wt0;
    dst[d * 262144 + r * 32768 + (k >> 2) * 512 + c * 4 + (k & 3)] = w[i];
}

// -------------------- 3) gx GEMM (fp32 SIMT, f32x2 inner product) -----------
__global__ void __launch_bounds__(256) k_gemm(const float* __restrict__ W,
                                              const float* __restrict__ bias,
                                              int layer) {
    __shared__ float As[16][128];
    __shared__ float Ws[16][128];
    const int K = layer ? 512 : 256;
    const float* __restrict__ Ad = layer ? g_y0 : g_x0;
    const int tid = threadIdx.x;
    const int tx = tid & 15, ty = tid >> 4;
    const int m0 = blockIdx.y * 128, n0 = blockIdx.x * 128;
    const int d = blockIdx.z;
    const float* Wd = W + (size_t)d * 1024 * K;
    const float* bd = bias + d * 1024;
    float* Cd = g_gx + (size_t)d * BT * 1024;
    const int lr = tid >> 2;
    const int lc = (tid & 3) * 4;

    unsigned long long accp[8][4];
#pragma unroll
    for (int i = 0; i < 8; i++)
#pragma unroll
        for (int j = 0; j < 4; j++) accp[i][j] = 0ull;

    for (int k0 = 0; k0 < K; k0 += 16) {
        float4 a0 = *(const float4*)&Ad[(size_t)(m0 + lr) * K + k0 + lc];
        float4 a1 = *(const float4*)&Ad[(size_t)(m0 + lr + 64) * K + k0 + lc];
        float4 w0 = *(const float4*)&Wd[(size_t)(n0 + lr) * K + k0 + lc];
        float4 w1 = *(const float4*)&Wd[(size_t)(n0 + lr + 64) * K + k0 + lc];
        __syncthreads();
        As[lc + 0][lr] = a0.x; As[lc + 1][lr] = a0.y; As[lc + 2][lr] = a0.z; As[lc + 3][lr] = a0.w;
        As[lc + 0][lr + 64] = a1.x; As[lc + 1][lr + 64] = a1.y; As[lc + 2][lr + 64] = a1.z; As[lc + 3][lr + 64] = a1.w;
        Ws[lc + 0][lr] = w0.x; Ws[lc + 1][lr] = w0.y; Ws[lc + 2][lr] = w0.z; Ws[lc + 3][lr] = w0.w;
        Ws[lc + 0][lr + 64] = w1.x; Ws[lc + 1][lr + 64] = w1.y; Ws[lc + 2][lr + 64] = w1.z; Ws[lc + 3][lr + 64] = w1.w;
        __syncthreads();
#pragma unroll
        for (int kk = 0; kk < 16; kk++) {
            float4 af0 = *(const float4*)&As[kk][ty * 8];
            float4 af1 = *(const float4*)&As[kk][ty * 8 + 4];
            float4 wf0 = *(const float4*)&Ws[kk][tx * 8];
            float4 wf1 = *(const float4*)&Ws[kk][tx * 8 + 4];
            unsigned long long wp0 = packpair(wf0.x, wf0.y);
            unsigned long long wp1 = packpair(wf0.z, wf0.w);
            unsigned long long wp2 = packpair(wf1.x, wf1.y);
            unsigned long long wp3 = packpair(wf1.z, wf1.w);
            float a[8] = {af0.x, af0.y, af0.z, af0.w, af1.x, af1.y, af1.z, af1.w};
#pragma unroll
            for (int i = 0; i < 8; i++) {
                unsigned long long ap = pack2(a[i]);
                fma2(accp[i][0], ap, wp0);
                fma2(accp[i][1], ap, wp1);
                fma2(accp[i][2], ap, wp2);
                fma2(accp[i][3], ap, wp3);
            }
        }
    }
    float bv[8];
#pragma unroll
    for (int j = 0; j < 8; j++) bv[j] = bd[n0 + tx * 8 + j];
#pragma unroll
    for (int i = 0; i < 8; i++) {
        int m = m0 + ty * 8 + i;
        float o[8];
#pragma unroll
        for (int j = 0; j < 4; j++) unpack2(accp[i][j], o[2 * j], o[2 * j + 1]);
        float4 o0 = make_float4(o[0] + bv[0], o[1] + bv[1], o[2] + bv[2], o[3] + bv[3]);
        float4 o1 = make_float4(o[4] + bv[4], o[5] + bv[5], o[6] + bv[6], o[7] + bv[7]);
        *(float4*)&Cd[(size_t)m * 1024 + n0 + tx * 8] = o0;
        *(float4*)&Cd[(size_t)m * 1024 + n0 + tx * 8 + 4] = o1;
    }
}

// -------------------- 4) LSTM recurrence: 2 interleaved groups per CTA ------
// 64 CTAs: bx = d*32 + r*4 + gp; CTA handles groups {2gp, 2gp+1} (same W!).
// Step = two half-steps.  Half-step for group G:
//   [per-warp: poll G's 2 peer flags, ldcg + STS transpose, syncwarp]
//   GEMV(G) -> part(G);  barrier;
//   fused combine+update(G): h -> hl(G) own slice + coalesced hx publish;
//   barrier;  tid0 releases G's flag;  y store.
// The release of group A lands mid-step, so consumers' wait-A next step has a
// full B-phase of slack (and vice versa) -> exchange latency hidden under the
// other group's compute.  Per-group dataflow identical to the proven
// single-group kernel, so buffer/flag safety arguments carry over unchanged.
__global__ void __launch_bounds__(256) k_lstm(int layer) {
    extern __shared__ float sm[];
    float* wsm = sm + SM_W;

    const int tid = threadIdx.x;
    const int bx  = blockIdx.x;       // 0..63
    const int d   = bx >> 5;
    const int r   = (bx >> 2) & 7;
    const int gp  = bx & 3;
    const float* wt = layer ? g_wt1 : g_wt0;
    float* y = layer ? g_y1 : g_y0;
    const float* gxd = g_gx + (size_t)d * BT * 1024;
    const int beta = layer * Tlen;

    // load W slice (shared by both groups), zero both h buffers
    {
        const float4* src4 = (const float4*)(wt + d * 262144 + r * 32768);
        float4* dst = (float4*)wsm;
        for (int i = tid; i < 8192; i += 256) dst[i] = src4[i];
        for (int i = tid; i < 2 * 2048; i += 256) sm[SM_HL + i] = 0.0f;
    }
    __syncthreads();

    // GEMV mapping
    const int c    = tid & 63;     // columns c and c+64
    const int kq   = tid >> 6;     // K-quarter — uniform within warp pair
    const int lane = tid & 31;
    // fused combine+update mapping: (batch cb, unit cq)
    const int cb   = tid >> 5;
    const int cq   = tid & 31;
    const int gxbase_col = r * 32 + cq;   // + gate*256

    const ulonglong2* wsmp = (const ulonglong2*)wsm;
    float creg[2] = {0.0f, 0.0f};

    for (int s = 0; s < Tlen; s++) {
        const int t = d ? (Tlen - 1 - s) : s;

#pragma unroll
        for (int grp = 0; grp < 2; grp++) {
            const int gg = gp * 2 + grp;
            const int b0 = gg * 8;
            float* hl   = sm + SM_HL + grp * 2048;      // [8 b][256 k]
            float* part = sm + SM_PART + grp * 4096;    // [4 kq][8 b][128 col]
            float4* part4 = (float4*)part;
            float* hx_grp   = g_hx + ((d * 8 + gg) * 2) * 2048;
            int*   flag_grp = g_flag + (d * 8 + gg) * 8 * FPAD;

            // gx prefetch (consumed ~GEMV later; LDG latency hidden)
            const float* gxp = gxd + ((size_t)(b0 + cb) * Tlen + t) * 1024 + gxbase_col;
            float gxi = gxp[0];
            float gxf = gxp[256];
            float gxg = gxp[512];
            float gxo = gxp[768];

            // ---- exchange-in (per-warp, no block barrier) ----
            if (s > 0) {
                const float4* hxb = (const float4*)(hx_grp + (s & 1) * 2048);
#pragma unroll
                for (int e = 0; e < 2; e++) {
                    const int rr = 2 * kq + e;
                    if (rr != r) {
                        const int* fp = flag_grp + rr * FPAD;
                        while (flag_load_acquire(fp) < beta + s) { }
                        float4 v0 = __ldcg(hxb + rr * 64 + lane);
                        float4 v1 = __ldcg(hxb + rr * 64 + lane + 32);
                        const int ub0 = lane >> 3;
                        const int uj  = (lane & 7) * 4;
                        *(float4*)&hl[ub0 * 256 + rr * 32 + uj]       = v0;
                        *(float4*)&hl[(ub0 + 4) * 256 + rr * 32 + uj] = v1;
                    }
                }
                __syncwarp();
            }

            // ---- GEMV: 2 cols x 8 batches over K-quarter, k-pair f32x2 ----
            unsigned long long acc0[8], acc1[8];
#pragma unroll
            for (int b = 0; b < 8; b++) { acc0[b] = 0ull; acc1[b] = 0ull; }
            const int q0 = kq * 16;
#pragma unroll 4
            for (int q = 0; q < 16; q++) {
                ulonglong2 wA = wsmp[(q0 + q) * 128 + c];
                ulonglong2 wB = wsmp[(q0 + q) * 128 + c + 64];
                const float* hb = hl + (q0 + q) * 4;
#pragma unroll
                for (int b = 0; b < 8; b++) {
                    ulonglong2 hp = *(const ulonglong2*)(hb + b * 256);
                    fma2(acc0[b], wA.x, hp.x); fma2(acc0[b], wA.y, hp.y);
                    fma2(acc1[b], wB.x, hp.x); fma2(acc1[b], wB.y, hp.y);
                }
            }
#pragma unroll
            for (int b = 0; b < 8; b++) {
                float lo, hi;
                unpack2(acc0[b], lo, hi);
                part[(kq * 8 + b) * 128 + c] = lo + hi;
                unpack2(acc1[b], lo, hi);
                part[(kq * 8 + b) * 128 + c + 64] = lo + hi;
            }
            __syncthreads();

            // ---- fused combine + update: (cb, cq) owns unit cq of batch cb ----
            float hreg;
            {
                float4 p0 = part4[(0 * 8 + cb) * 32 + cq];   // (i,f,g,o) partials
                float4 p1 = part4[(1 * 8 + cb) * 32 + cq];
                float4 p2 = part4[(2 * 8 + cb) * 32 + cq];
                float4 p3 = part4[(3 * 8 + cb) * 32 + cq];
                float gi = p0.x + p1.x + p2.x + p3.x + gxi;
                float gf = p0.y + p1.y + p2.y + p3.y + gxf;
                float gg2 = p0.z + p1.z + p2.z + p3.z + gxg;
                float go = p0.w + p1.w + p2.w + p3.w + gxo;
                creg[grp] = sigm(gf) * creg[grp] + sigm(gi) * tanhf(gg2);
                hreg = sigm(go) * tanhf(creg[grp]);
                hl[cb * 256 + r * 32 + cq] = hreg;           // own slice, [b][k]
                if (s + 1 < Tlen)                            // coalesced publish
                    hx_grp[((s + 1) & 1) * 2048 + r * 256 + cb * 32 + cq] = hreg;
            }
            __syncthreads();   // hl/hx stores complete CTA-wide before release

            if (s + 1 < Tlen && tid == 0)
                flag_store_release(flag_grp + r * FPAD, beta + s + 1);

            // y store AFTER flag publish: off the inter-CTA critical path
            y[((size_t)(b0 + cb) * Tlen + t) * 512 + d * 256 + r * 32 + cq] = hreg;
        }
    }
}

// -------------------- 5) emissions = y1 @ lin_w^T + lin_b -------------------
__global__ void __launch_bounds__(256) k_linear(const float* __restrict__ lw,
                                                const float* __restrict__ lb) {
    __shared__ float ws[Lnum * 512];
    __shared__ float bs[Lnum];
    const int tid = threadIdx.x;
    for (int i = tid; i < Lnum * 512; i += 256) ws[i] = lw[i];
    if (tid < Lnum) bs[tid] = lb[tid];
    __syncthreads();
    const int warp = tid >> 5, lane = tid & 31;
    const int pos = blockIdx.x * 8 + warp;
    const float* yp = g_y1 + (size_t)pos * 512;
    float acc[Lnum];
#pragma unroll
    for (int l = 0; l < Lnum; l++) acc[l] = 0.0f;
    for (int k = lane; k < 512; k += 32) {
        float yv = yp[k];
#pragma unroll
        for (int l = 0; l < Lnum; l++) acc[l] = fmaf(yv, ws[l * 512 + k], acc[l]);
    }
#pragma unroll
    for (int l = 0; l < Lnum; l++)
#pragma unroll
        for (int o = 16; o > 0; o >>= 1) acc[l] += __shfl_xor_sync(0xffffffffu, acc[l], o);
    if (lane < Lnum) g_em[(size_t)pos * Lnum + lane] = acc[lane] + bs[lane];
}

// -------------------- 6) CRF NLL --------------------------------------------
__global__ void k_crf(const int* __restrict__ labels, const int* __restrict__ mask,
                      const float* __restrict__ trans, const float* __restrict__ startt,
                      const float* __restrict__ endt) {
    const int b = blockIdx.x;
    const int lane = threadIdx.x;
    __shared__ float salpha[Lnum];
    const float* em = g_em + (size_t)b * Tlen * Lnum;
    const int* lab = labels + b * Tlen;
    const int* msk = mask + b * Tlen;
    const int j = (lane < Lnum) ? lane : 0;

    float tr[Lnum];
#pragma unroll
    for (int i = 0; i < Lnum; i++) tr[i] = trans[i * Lnum + j];

    int mcount = 0;
    for (int t = lane; t < Tlen; t += 32) mcount += msk[t];
#pragma unroll
    for (int o = 16; o > 0; o >>= 1) mcount += __shfl_xor_sync(0xffffffffu, mcount, o);
    float sc = 0.0f;
    for (int t = lane + 1; t < Tlen; t += 32)
        if (msk[t]) sc += trans[lab[t - 1] * Lnum + lab[t]] + em[t * Lnum + lab[t]];
#pragma unroll
    for (int o = 16; o > 0; o >>= 1) sc += __shfl_xor_sync(0xffffffffu, sc, o);

    float alpha = startt[j] + em[j];
    for (int t = 1; t < Tlen; t++) {
        if (lane < Lnum) salpha[lane] = alpha;
        __syncwarp();
        float vs[Lnum];
        float m = -1e30f;
#pragma unroll
        for (int i = 0; i < Lnum; i++) {
            vs[i] = salpha[i] + tr[i];
            m = fmaxf(m, vs[i]);
        }
        float ssum = 0.0f;
#pragma unroll
        for (int i = 0; i < Lnum; i++) ssum += __expf(vs[i] - m);
        float na = m + __logf(ssum) + em[t * Lnum + j];
        if (msk[t]) alpha = na;
        __syncwarp();
    }
    float v = (lane < Lnum) ? alpha + endt[lane] : -1e30f;
    float mm = v;
#pragma unroll
    for (int o = 16; o > 0; o >>= 1) mm = fmaxf(mm, __shfl_xor_sync(0xffffffffu, mm, o));
    float e = (lane < Lnum) ? __expf(v - mm) : 0.0f;
#pragma unroll
    for (int o = 16; o > 0; o >>= 1) e += __shfl_xor_sync(0xffffffffu, e, o);
    float logZ = mm + __logf(e);

    if (lane == 0) {
        sc += startt[lab[0]] + em[lab[0]] + endt[lab[mcount - 1]];
        g_partial[b] = logZ - sc;
    }
}

// -------------------- 7) mean reduce ----------------------------------------
__global__ void k_final(float* __restrict__ out) {
    __shared__ float s[Bsz];
    const int tid = threadIdx.x;
    s[tid] = g_partial[tid];
    __syncthreads();
    for (int o = 32; o > 0; o >>= 1) {
        if (tid < o) s[tid] += s[tid + o];
        __syncthreads();
    }
    if (tid == 0) out[0] = s[0] * (1.0f / (float)Bsz);
}

// ---------------------------------------------------------------------------
extern "C" void kernel_launch(void* const* d_in, const int* in_sizes, int n_in,
                              void* d_out, int out_size) {
    (void)in_sizes; (void)n_in; (void)out_size;
    const int*   input_ids = (const int*)d_in[0];
    const int*   attn      = (const int*)d_in[1];
    const int*   labels    = (const int*)d_in[2];
    const float* emb       = (const float*)d_in[3];
    const float* w_ih0     = (const float*)d_in[4];
    const float* w_hh0     = (const float*)d_in[5];
    const float* b0        = (const float*)d_in[6];
    const float* w_ih1     = (const float*)d_in[7];
    const float* w_hh1     = (const float*)d_in[8];
    const float* b1        = (const float*)d_in[9];
    const float* lin_w     = (const float*)d_in[10];
    const float* lin_b     = (const float*)d_in[11];
    const float* trans     = (const float*)d_in[12];
    const float* startt    = (const float*)d_in[13];
    const float* endt      = (const float*)d_in[14];
    float* out = (float*)d_out;

    cudaFuncSetAttribute(k_lstm, cudaFuncAttributeMaxDynamicSharedMemorySize, SM_BYTES);

    k_embed<<<(BT * (Emb / 4) + 255) / 256, 256>>>(input_ids, emb);    // 0
    k_gemm<<<dim3(8, 256, 2), 256>>>(w_ih0, b0, 0);                    // 1
    k_trans<<<(2 * 1024 * 256 + 255) / 256, 256>>>(w_hh0, 0);          // 2
    k_lstm<<<64, 256, SM_BYTES>>>(0);                                  // 3

    k_trans<<<(2 * 1024 * 256 + 255) / 256, 256>>>(w_hh1, 1);          // 4
    k_gemm<<<dim3(8, 256, 2), 256>>>(w_ih1, b1, 1);                    // 5
    k_lstm<<<64, 256, SM_BYTES>>>(1);                                  // 6

    k_linear<<<BT / 8, 256>>>(lin_w, lin_b);
    k_crf<<<Bsz, 32>>>(labels, attn, trans, startt, endt);
    k_final<<<1, 64>>>(out);
}

// round 17
// speedup vs baseline: 1.5917x; 1.5917x over previous
#include <cuda_runtime.h>
#include <cuda_bf16.h>

// ---------------------------------------------------------------------------
// BiLSTM-CRF forward loss.  B=64, T=512, V=50000, E=256, H=256, L=9.
// embed -> gemm(gx,l0,f32x2) -> lstm(l0: split-K/4, 2-col threads, per-warp
//   L2 h-exchange with joint flag wait + MLP-4 loads) -> gemm/lstm(l1)
//   -> linear -> CRF NLL -> mean.
// ---------------------------------------------------------------------------

#define Bsz  64
#define Tlen 512
#define Emb  256
#define Hd   256
#define Lnum 9
#define BT   (Bsz * Tlen)   // 32768

// dynamic smem layout for k_lstm (float offsets)
#define SM_W    0          // [32768] w slice (rank): [k/4][128 cols][4]
#define SM_HL   32768      // [8 b][256 k]  h, batch-major
#define SM_G    34816      // [8][128]  gates per batch
#define SM_PART 35840      // [4 kq][8 b][128 col] split-K partial sums
#define SM_BYTES ((SM_PART + 4096) * 4)   // 159,744 B

#define FPAD 32            // ints per flag (one 128 B line each)

// -------------------- scratch (device globals; no allocs) -------------------
__device__ float g_x0[(size_t)BT * Emb];
__device__ float g_gx[2ull * BT * 1024];
__device__ float g_y0[(size_t)BT * 512];
__device__ float g_y1[(size_t)BT * 512];
__device__ float g_wt0[2 * 256 * 1024];
__device__ float g_wt1[2 * 256 * 1024];
__device__ float g_em[(size_t)BT * Lnum];
__device__ float g_partial[Bsz];
// h exchange: [d][g][buf][8 ranks][[ub(8)][ujj(32)]]
__device__ float g_hx[2 * 8 * 2 * 2048];
__device__ int   g_flag[2 * 8 * 8 * FPAD];

__device__ __forceinline__ float sigm(float x) { return 1.0f / (1.0f + __expf(-x)); }

__device__ __forceinline__ void fma2(unsigned long long& acc,
                                     unsigned long long a, unsigned long long b) {
    asm("fma.rn.f32x2 %0, %1, %2, %0;" : "+l"(acc) : "l"(a), "l"(b));
}
__device__ __forceinline__ unsigned long long pack2(float f) {
    unsigned long long r;
    asm("mov.b64 %0, {%1, %1};" : "=l"(r) : "f"(f));
    return r;
}
__device__ __forceinline__ unsigned long long packpair(float lo, float hi) {
    unsigned long long r;
    asm("mov.b64 %0, {%1, %2};" : "=l"(r) : "f"(lo), "f"(hi));
    return r;
}
__device__ __forceinline__ void unpack2(unsigned long long v, float& lo, float& hi) {
    asm("mov.b64 {%0, %1}, %2;" : "=f"(lo), "=f"(hi) : "l"(v));
}
__device__ __forceinline__ void flag_store_release(int* p, int v) {
    asm volatile("st.release.gpu.s32 [%0], %1;" :: "l"(p), "r"(v) : "memory");
}
__device__ __forceinline__ int flag_load_acquire(const int* p) {
    int v;
    asm volatile("ld.acquire.gpu.s32 %0, [%1];" : "=r"(v) : "l"(p) : "memory");
    return v;
}

// -------------------- 1) embedding gather (float4) --------------------------
__global__ void k_embed(const int* __restrict__ ids, const float* __restrict__ emb) {
    int i = blockIdx.x * blockDim.x + threadIdx.x;
    if (i >= BT * (Emb / 4)) return;
    int pos = i >> 6;
    int e4  = i & 63;
    ((float4*)g_x0)[i] = ((const float4*)emb)[(size_t)ids[pos] * (Emb / 4) + e4];
}

// -------- 2) w_hh relayout [2][1024][256] -> [d][rank][k/4][128 cols][4] ----
// Gate-major columns (c = gate*32 + unit), as in the 6,497us champion.
__global__ void k_trans(const float* __restrict__ w, int layer) {
    int i = blockIdx.x * blockDim.x + threadIdx.x;
    if (i < 2 * 8 * 8 * FPAD) g_flag[i] = 0;
    if (i >= 2 * 1024 * 256) return;
    int d   = i >> 18;
    int row = (i >> 8) & 1023;
    int k   = i & 255;
    int g   = row >> 8;
    int r   = (row & 255) >> 5;
    int jj  = row & 31;
    int c   = g * 32 + jj;
    float* dst = layer ? g_wt1 : g_wt0;
    dst[d * 262144 + r * 32768 + (k >> 2) * 512 + c * 4 + (k & 3)] = w[i];
}

// -------------------- 3) gx GEMM (fp32 SIMT, f32x2 inner product) -----------
__global__ void __launch_bounds__(256) k_gemm(const float* __restrict__ W,
                                              const float* __restrict__ bias,
                                              int layer) {
    __shared__ float As[16][128];
    __shared__ float Ws[16][128];
    const int K = layer ? 512 : 256;
    const float* __restrict__ Ad = layer ? g_y0 : g_x0;
    const int tid = threadIdx.x;
    const int tx = tid & 15, ty = tid >> 4;
    const int m0 = blockIdx.y * 128, n0 = blockIdx.x * 128;
    const int d = blockIdx.z;
    const float* Wd = W + (size_t)d * 1024 * K;
    const float* bd = bias + d * 1024;
    float* Cd = g_gx + (size_t)d * BT * 1024;
    const int lr = tid >> 2;
    const int lc = (tid & 3) * 4;

    unsigned long long accp[8][4];
#pragma unroll
    for (int i = 0; i < 8; i++)
#pragma unroll
        for (int j = 0; j < 4; j++) accp[i][j] = 0ull;

    for (int k0 = 0; k0 < K; k0 += 16) {
        float4 a0 = *(const float4*)&Ad[(size_t)(m0 + lr) * K + k0 + lc];
        float4 a1 = *(const float4*)&Ad[(size_t)(m0 + lr + 64) * K + k0 + lc];
        float4 w0 = *(const float4*)&Wd[(size_t)(n0 + lr) * K + k0 + lc];
        float4 w1 = *(const float4*)&Wd[(size_t)(n0 + lr + 64) * K + k0 + lc];
        __syncthreads();
        As[lc + 0][lr] = a0.x; As[lc + 1][lr] = a0.y; As[lc + 2][lr] = a0.z; As[lc + 3][lr] = a0.w;
        As[lc + 0][lr + 64] = a1.x; As[lc + 1][lr + 64] = a1.y; As[lc + 2][lr + 64] = a1.z; As[lc + 3][lr + 64] = a1.w;
        Ws[lc + 0][lr] = w0.x; Ws[lc + 1][lr] = w0.y; Ws[lc + 2][lr] = w0.z; Ws[lc + 3][lr] = w0.w;
        Ws[lc + 0][lr + 64] = w1.x; Ws[lc + 1][lr + 64] = w1.y; Ws[lc + 2][lr + 64] = w1.z; Ws[lc + 3][lr + 64] = w1.w;
        __syncthreads();
#pragma unroll
        for (int kk = 0; kk < 16; kk++) {
            float4 af0 = *(const float4*)&As[kk][ty * 8];
            float4 af1 = *(const float4*)&As[kk][ty * 8 + 4];
            float4 wf0 = *(const float4*)&Ws[kk][tx * 8];
            float4 wf1 = *(const float4*)&Ws[kk][tx * 8 + 4];
            unsigned long long wp0 = packpair(wf0.x, wf0.y);
            unsigned long long wp1 = packpair(wf0.z, wf0.w);
            unsigned long long wp2 = packpair(wf1.x, wf1.y);
            unsigned long long wp3 = packpair(wf1.z, wf1.w);
            float a[8] = {af0.x, af0.y, af0.z, af0.w, af1.x, af1.y, af1.z, af1.w};
#pragma unroll
            for (int i = 0; i < 8; i++) {
                unsigned long long ap = pack2(a[i]);
                fma2(accp[i][0], ap, wp0);
                fma2(accp[i][1], ap, wp1);
                fma2(accp[i][2], ap, wp2);
                fma2(accp[i][3], ap, wp3);
            }
        }
    }
    float bv[8];
#pragma unroll
    for (int j = 0; j < 8; j++) bv[j] = bd[n0 + tx * 8 + j];
#pragma unroll
    for (int i = 0; i < 8; i++) {
        int m = m0 + ty * 8 + i;
        float o[8];
#pragma unroll
        for (int j = 0; j < 4; j++) unpack2(accp[i][j], o[2 * j], o[2 * j + 1]);
        float4 o0 = make_float4(o[0] + bv[0], o[1] + bv[1], o[2] + bv[2], o[3] + bv[3]);
        float4 o1 = make_float4(o[4] + bv[4], o[5] + bv[5], o[6] + bv[6], o[7] + bv[7]);
        *(float4*)&Cd[(size_t)m * 1024 + n0 + tx * 8] = o0;
        *(float4*)&Cd[(size_t)m * 1024 + n0 + tx * 8 + 4] = o1;
    }
}

// -------------------- 4) LSTM recurrence (champion + MLP-4 exchange) --------
// 128 plain CTAs: bx = d*64 + r*8 + g.  Rank r owns 32 hidden units (128 gate
// cols) for batch group g (8 batches).  W slice (128 KB) in SMEM.
// GEMV: thread (c in 0..63, kq in 0..3) computes cols {c, c+64} over K-quarter
// kq.  Exchange-in per warp: JOINT poll of both needed flags, then ALL 4
// ldcg loads issued back-to-back (MLP 4), then STS transpose, syncwarp.
__global__ void __launch_bounds__(256) k_lstm(int layer) {
    extern __shared__ float sm[];
    float* wsm  = sm + SM_W;
    float* hl   = sm + SM_HL;      // [8 b][256 k]
    float* gsm  = sm + SM_G;       // [8][128]
    float* part = sm + SM_PART;    // [4 kq][8 b][128 col]

    const int tid = threadIdx.x;
    const int bx  = blockIdx.x;
    const int d   = bx >> 6;
    const int r   = (bx >> 3) & 7;
    const int g   = bx & 7;
    const int b0  = g * 8;
    const float* wt = layer ? g_wt1 : g_wt0;
    float* y = layer ? g_y1 : g_y0;
    const float* gxd = g_gx + (size_t)d * BT * 1024;
    const int beta = layer * Tlen;

    float* hx_grp   = g_hx + ((d * 8 + g) * 2) * 2048;        // + buf*2048
    int*   flag_grp = g_flag + (d * 8 + g) * 8 * FPAD;         // + src*FPAD

    // load W slice into smem, zero h
    {
        const float4* src4 = (const float4*)(wt + d * 262144 + r * 32768);
        float4* dst = (float4*)wsm;
        for (int i = tid; i < 8192; i += 256) dst[i] = src4[i];
        for (int i = tid; i < 2048; i += 256) hl[i] = 0.0f;
    }
    __syncthreads();

    // GEMV mapping
    const int c    = tid & 63;     // columns c and c+64
    const int kq   = tid >> 6;     // K-quarter — uniform within warp pair
    const int lane = tid & 31;
    // update mapping
    const int ub   = tid >> 5;
    const int ujj  = tid & 31;
    // combine mapping: (batch cb, 4-col group cq)
    const int cb   = tid >> 5;
    const int cq   = tid & 31;
    const int gxcol4 = (cq >> 3) * 256 + r * 32 + (cq & 7) * 4;

    // exchange: ranks this warp needs
    const int r0 = 2 * kq, r1 = 2 * kq + 1;
    const bool nd0 = (r0 != r), nd1 = (r1 != r);
    const int* fp0 = flag_grp + r0 * FPAD;
    const int* fp1 = flag_grp + r1 * FPAD;

    const ulonglong2* wsmp = (const ulonglong2*)wsm;
    float4* part4 = (float4*)part;
    float creg = 0.0f;

    for (int s = 0; s < Tlen; s++) {
        const int t = d ? (Tlen - 1 - s) : s;

        // gx prefetch (combine mapping; issued early to hide DRAM latency)
        const float4 gx4 = *(const float4*)&gxd[((size_t)(b0 + cb) * Tlen + t) * 1024 + gxcol4];

        // ---- exchange-in: joint flag wait, MLP-4 loads, then STS ----
        if (s > 0) {
            const float4* hxb = (const float4*)(hx_grp + (s & 1) * 2048);
            const int want = beta + s;
            for (;;) {
                bool ok0 = !nd0 || (flag_load_acquire(fp0) >= want);
                bool ok1 = !nd1 || (flag_load_acquire(fp1) >= want);
                if (ok0 && ok1) break;
            }
            float4 a0, a1, b0v, b1v;
            if (nd0) {
                a0 = __ldcg(hxb + r0 * 64 + lane);
                a1 = __ldcg(hxb + r0 * 64 + lane + 32);
            }
            if (nd1) {
                b0v = __ldcg(hxb + r1 * 64 + lane);
                b1v = __ldcg(hxb + r1 * 64 + lane + 32);
            }
            const int ub0 = lane >> 3;
            const int uj  = (lane & 7) * 4;
            if (nd0) {
                *(float4*)&hl[ub0 * 256 + r0 * 32 + uj]       = a0;
                *(float4*)&hl[(ub0 + 4) * 256 + r0 * 32 + uj] = a1;
            }
            if (nd1) {
                *(float4*)&hl[ub0 * 256 + r1 * 32 + uj]       = b0v;
                *(float4*)&hl[(ub0 + 4) * 256 + r1 * 32 + uj] = b1v;
            }
            __syncwarp();   // cross-lane STS -> LDS within warp
        }

        // ---- GEMV: 2 cols x 8 batches over K-quarter, k-pair f32x2 ----
        unsigned long long acc0[8], acc1[8];
#pragma unroll
        for (int b = 0; b < 8; b++) { acc0[b] = 0ull; acc1[b] = 0ull; }
        const int q0 = kq * 16;
#pragma unroll 4
        for (int q = 0; q < 16; q++) {
            ulonglong2 wA = wsmp[(q0 + q) * 128 + c];
            ulonglong2 wB = wsmp[(q0 + q) * 128 + c + 64];
            const float* hb = hl + (q0 + q) * 4;
#pragma unroll
            for (int b = 0; b < 8; b++) {
                ulonglong2 hp = *(const ulonglong2*)(hb + b * 256);
                fma2(acc0[b], wA.x, hp.x); fma2(acc0[b], wA.y, hp.y);
                fma2(acc1[b], wB.x, hp.x); fma2(acc1[b], wB.y, hp.y);
            }
        }
#pragma unroll
        for (int b = 0; b < 8; b++) {
            float lo, hi;
            unpack2(acc0[b], lo, hi);
            part[(kq * 8 + b) * 128 + c] = lo + hi;
            unpack2(acc1[b], lo, hi);
            part[(kq * 8 + b) * 128 + c + 64] = lo + hi;
        }
        __syncthreads();

        // ---- combine 4 partials + gx -> gates (float4 per thread) ----
        {
            float4 p0 = part4[(0 * 8 + cb) * 32 + cq];
            float4 p1 = part4[(1 * 8 + cb) * 32 + cq];
            float4 p2 = part4[(2 * 8 + cb) * 32 + cq];
            float4 p3 = part4[(3 * 8 + cb) * 32 + cq];
            float4 o;
            o.x = p0.x + p1.x + p2.x + p3.x + gx4.x;
            o.y = p0.y + p1.y + p2.y + p3.y + gx4.y;
            o.z = p0.z + p1.z + p2.z + p3.z + gx4.z;
            o.w = p0.w + p1.w + p2.w + p3.w + gx4.w;
            *(float4*)&gsm[cb * 128 + cq * 4] = o;
        }
        __syncthreads();

        // ---- update: thread owns (ub, ujj); c in register; publish direct ----
        float hreg;
        {
            float gi = gsm[ub * 128 + ujj];
            float gf = gsm[ub * 128 + 32 + ujj];
            float gg = gsm[ub * 128 + 64 + ujj];
            float go = gsm[ub * 128 + 96 + ujj];
            creg = sigm(gf) * creg + sigm(gi) * tanhf(gg);
            hreg = sigm(go) * tanhf(creg);
            hl[ub * 256 + r * 32 + ujj] = hreg;          // own slice, [b][k]
            if (s + 1 < Tlen)                            // coalesced [ub][ujj] publish
                hx_grp[((s + 1) & 1) * 2048 + r * 256 + ub * 32 + ujj] = hreg;
        }
        __syncthreads();   // hl/hx stores complete CTA-wide before release

        if (s + 1 < Tlen && tid == 0)
            flag_store_release(flag_grp + r * FPAD, beta + s + 1);

        // y store AFTER flag publish: off the inter-CTA critical path
        y[((size_t)(b0 + ub) * Tlen + t) * 512 + d * 256 + r * 32 + ujj] = hreg;
    }
}

// -------------------- 5) emissions = y1 @ lin_w^T + lin_b -------------------
__global__ void __launch_bounds__(256) k_linear(const float* __restrict__ lw,
                                                const float* __restrict__ lb) {
    __shared__ float ws[Lnum * 512];
    __shared__ float bs[Lnum];
    const int tid = threadIdx.x;
    for (int i = tid; i < Lnum * 512; i += 256) ws[i] = lw[i];
    if (tid < Lnum) bs[tid] = lb[tid];
    __syncthreads();
    const int warp = tid >> 5, lane = tid & 31;
    const int pos = blockIdx.x * 8 + warp;
    const float* yp = g_y1 + (size_t)pos * 512;
    float acc[Lnum];
#pragma unroll
    for (int l = 0; l < Lnum; l++) acc[l] = 0.0f;
    for (int k = lane; k < 512; k += 32) {
        float yv = yp[k];
#pragma unroll
        for (int l = 0; l < Lnum; l++) acc[l] = fmaf(yv, ws[l * 512 + k], acc[l]);
    }
#pragma unroll
    for (int l = 0; l < Lnum; l++)
#pragma unroll
        for (int o = 16; o > 0; o >>= 1) acc[l] += __shfl_xor_sync(0xffffffffu, acc[l], o);
    if (lane < Lnum) g_em[(size_t)pos * Lnum + lane] = acc[lane] + bs[lane];
}

// -------------------- 6) CRF NLL --------------------------------------------
__global__ void k_crf(const int* __restrict__ labels, const int* __restrict__ mask,
                      const float* __restrict__ trans, const float* __restrict__ startt,
                      const float* __restrict__ endt) {
    const int b = blockIdx.x;
    const int lane = threadIdx.x;
    __shared__ float salpha[Lnum];
    const float* em = g_em + (size_t)b * Tlen * Lnum;
    const int* lab = labels + b * Tlen;
    const int* msk = mask + b * Tlen;
    const int j = (lane < Lnum) ? lane : 0;

    float tr[Lnum];
#pragma unroll
    for (int i = 0; i < Lnum; i++) tr[i] = trans[i * Lnum + j];

    int mcount = 0;
    for (int t = lane; t < Tlen; t += 32) mcount += msk[t];
#pragma unroll
    for (int o = 16; o > 0; o >>= 1) mcount += __shfl_xor_sync(0xffffffffu, mcount, o);
    float sc = 0.0f;
    for (int t = lane + 1; t < Tlen; t += 32)
        if (msk[t]) sc += trans[lab[t - 1] * Lnum + lab[t]] + em[t * Lnum + lab[t]];
#pragma unroll
    for (int o = 16; o > 0; o >>= 1) sc += __shfl_xor_sync(0xffffffffu, sc, o);

    float alpha = startt[j] + em[j];
    for (int t = 1; t < Tlen; t++) {
        if (lane < Lnum) salpha[lane] = alpha;
        __syncwarp();
        float vs[Lnum];
        float m = -1e30f;
#pragma unroll
        for (int i = 0; i < Lnum; i++) {
            vs[i] = salpha[i] + tr[i];
            m = fmaxf(m, vs[i]);
        }
        float ssum = 0.0f;
#pragma unroll
        for (int i = 0; i < Lnum; i++) ssum += __expf(vs[i] - m);
        float na = m + __logf(ssum) + em[t * Lnum + j];
        if (msk[t]) alpha = na;
        __syncwarp();
    }
    float v = (lane < Lnum) ? alpha + endt[lane] : -1e30f;
    float mm = v;
#pragma unroll
    for (int o = 16; o > 0; o >>= 1) mm = fmaxf(mm, __shfl_xor_sync(0xffffffffu, mm, o));
    float e = (lane < Lnum) ? __expf(v - mm) : 0.0f;
#pragma unroll
    for (int o = 16; o > 0; o >>= 1) e += __shfl_xor_sync(0xffffffffu, e, o);
    float logZ = mm + __logf(e);

    if (lane == 0) {
        sc += startt[lab[0]] + em[lab[0]] + endt[lab[mcount - 1]];
        g_partial[b] = logZ - sc;
    }
}

// -------------------- 7) mean reduce ----------------------------------------
__global__ void k_final(float* __restrict__ out) {
    __shared__ float s[Bsz];
    const int tid = threadIdx.x;
    s[tid] = g_partial[tid];
    __syncthreads();
    for (int o = 32; o > 0; o >>= 1) {
        if (tid < o) s[tid] += s[tid + o];
        __syncthreads();
    }
    if (tid == 0) out[0] = s[0] * (1.0f / (float)Bsz);
}

// ---------------------------------------------------------------------------
extern "C" void kernel_launch(void* const* d_in, const int* in_sizes, int n_in,
                              void* d_out, int out_size) {
    (void)in_sizes; (void)n_in; (void)out_size;
    const int*   input_ids = (const int*)d_in[0];
    const int*   attn      = (const int*)d_in[1];
    const int*   labels    = (const int*)d_in[2];
    const float* emb       = (const float*)d_in[3];
    const float* w_ih0     = (const float*)d_in[4];
    const float* w_hh0     = (const float*)d_in[5];
    const float* b0        = (const float*)d_in[6];
    const float* w_ih1     = (const float*)d_in[7];
    const float* w_hh1     = (const float*)d_in[8];
    const float* b1        = (const float*)d_in[9];
    const float* lin_w     = (const float*)d_in[10];
    const float* lin_b     = (const float*)d_in[11];
    const float* trans     = (const float*)d_in[12];
    const float* startt    = (const float*)d_in[13];
    const float* endt      = (const float*)d_in[14];
    float* out = (float*)d_out;

    cudaFuncSetAttribute(k_lstm, cudaFuncAttributeMaxDynamicSharedMemorySize, SM_BYTES);

    k_embed<<<(BT * (Emb / 4) + 255) / 256, 256>>>(input_ids, emb);    // 0
    k_gemm<<<dim3(8, 256, 2), 256>>>(w_ih0, b0, 0);                    // 1
    k_trans<<<(2 * 1024 * 256 + 255) / 256, 256>>>(w_hh0, 0);          // 2
    k_lstm<<<128, 256, SM_BYTES>>>(0);                                 // 3

    k_trans<<<(2 * 1024 * 256 + 255) / 256, 256>>>(w_hh1, 1);          // 4
    k_gemm<<<dim3(8, 256, 2), 256>>>(w_ih1, b1, 1);                    // 5
    k_lstm<<<128, 256, SM_BYTES>>>(1);                                 // 6

    k_linear<<<BT / 8, 256>>>(lin_w, lin_b);
    k_crf<<<Bsz, 32>>>(labels, attn, trans, startt, endt);
    k_final<<<1, 64>>>(out);
}